// round 1
// baseline (speedup 1.0000x reference)
#include <cuda_runtime.h>
#include <cstdint>

// Problem constants
#define NPTS 262144     // number of points (columns of xr)
#define DIMS 10         // variables
#define DD   286        // comb(13,3) veronese length
#define DPAD 288        // padded length (divisible by 8 and by P*2)

// 300 MB scratch: v_flat[r*NPTS + c] = monomial r evaluated at column c.
// Flat-read as q-vectors by k_quad (vq[n][i] = v_flat[n*286 + i]).
__device__ float g_scratch[(size_t)DD * NPTS];
// Transposed, zero-padded M: g_MT[j][i] = M_inv[i][j] (i,j < 286), else 0.
__device__ float g_MT[DPAD * DPAD];

// ---------------------------------------------------------------------------
// Kernel 0: transpose + zero-pad M_inv into MT[288][288]
// ---------------------------------------------------------------------------
__global__ void k_transpose(const float* __restrict__ M) {
    int idx = blockIdx.x * blockDim.x + threadIdx.x;
    if (idx >= DPAD * DPAD) return;
    int j = idx / DPAD;
    int i = idx - j * DPAD;
    g_MT[idx] = (i < DD && j < DD) ? M[i * DD + j] : 0.0f;
}

// ---------------------------------------------------------------------------
// Kernel 1: Veronese map. One thread handles 4 consecutive columns (float4).
// Row order matches the reference's _exponent_nk enumeration:
//   r=0: 1 ; r=1..10: x_j ; deg2: (j,k) j<=k, j-major ; deg3: (j,a,b) j<=a<=b.
// Multiply order matches reference: deg3 = (x_j*x_a)*x_b.
// ---------------------------------------------------------------------------
__device__ __forceinline__ float4 f4mul(float4 a, float4 b) {
    return make_float4(a.x * b.x, a.y * b.y, a.z * b.z, a.w * b.w);
}

__global__ void k_veronese(const float* __restrict__ X) {
    int t = blockIdx.x * blockDim.x + threadIdx.x;
    int c = t * 4;

    float4 y[DIMS];
#pragma unroll
    for (int k = 0; k < DIMS; k++)
        y[k] = *reinterpret_cast<const float4*>(X + (size_t)k * NPTS + c);

    int r = 0;
    *reinterpret_cast<float4*>(g_scratch + (size_t)r * NPTS + c) =
        make_float4(1.f, 1.f, 1.f, 1.f);
    r++;

#pragma unroll
    for (int j = 0; j < DIMS; j++) {
        *reinterpret_cast<float4*>(g_scratch + (size_t)r * NPTS + c) = y[j];
        r++;
    }

#pragma unroll
    for (int j = 0; j < DIMS; j++) {
#pragma unroll
        for (int a = j; a < DIMS; a++) {
            *reinterpret_cast<float4*>(g_scratch + (size_t)r * NPTS + c) =
                f4mul(y[j], y[a]);
            r++;
        }
    }

#pragma unroll
    for (int j = 0; j < DIMS; j++) {
#pragma unroll
        for (int a = j; a < DIMS; a++) {
            float4 t2 = f4mul(y[j], y[a]);
#pragma unroll
            for (int b = a; b < DIMS; b++) {
                *reinterpret_cast<float4*>(g_scratch + (size_t)r * NPTS + c) =
                    f4mul(t2, y[b]);
                r++;
            }
        }
    }
}

// ---------------------------------------------------------------------------
// Kernel 2: quadratic forms out[n] = q_n^T M q_n via packed f32x2 FMA.
//   Block = 256 threads = 32 groups x 8 i-slices; each thread owns 4 points
//   and a 36-float i-slice of each point's q vector (18 f32x2 register pairs).
//   Loop over j: t_j = sum_i q_i * M[i][j] (partial over slice), s += q_j * t_j,
//   final reduction across the 8 slices with shfl.xor.
// ---------------------------------------------------------------------------
constexpr int BM      = 128;          // points per block
constexpr int THREADS = 256;
constexpr int P       = 8;            // i-slices per point
constexpr int PTS     = 4;            // points per thread
constexpr int IK      = DPAD / P;     // 36 floats per slice
constexpr int KH      = IK / 2;       // 18 f32x2 pairs
constexpr int ROWQ    = 292;          // padded Qs row (292 % 32 == 4 -> no bank conflict)
constexpr int JSTAGE  = 8;            // MT rows staged per sync
constexpr int SMEM_BYTES = (BM * ROWQ + JSTAGE * DPAD) * 4;

__device__ __forceinline__ void fma2(unsigned long long& acc,
                                     unsigned long long a,
                                     unsigned long long b) {
    asm volatile("fma.rn.f32x2 %0, %1, %2, %0;" : "+l"(acc) : "l"(a), "l"(b));
}
__device__ __forceinline__ float pairsum(unsigned long long v) {
    float lo = __uint_as_float((unsigned int)v);
    float hi = __uint_as_float((unsigned int)(v >> 32));
    return lo + hi;
}

__global__ __launch_bounds__(THREADS, 1) void k_quad(float* __restrict__ out) {
    extern __shared__ float sm[];
    float* Qs = sm;                    // [BM][ROWQ]
    float* Mb = sm + BM * ROWQ;        // [JSTAGE][DPAD]

    const int tid = threadIdx.x;
    const int p   = tid & (P - 1);     // i-slice
    const int grp = tid >> 3;          // point group (0..31)
    const int base = blockIdx.x * (BM * DD);

    // Stage this block's 128 q-vectors (contiguous flat chunk) into smem.
    for (int l = tid; l < BM * DD; l += THREADS) {
        int n = l / DD;
        int i = l - n * DD;
        Qs[n * ROWQ + i] = g_scratch[base + l];
    }
    if (tid < BM) {                    // zero the i = 286,287 pad
        Qs[tid * ROWQ + 286] = 0.f;
        Qs[tid * ROWQ + 287] = 0.f;
    }
    __syncthreads();

    // Load this thread's q slices into paired registers.
    unsigned long long q[PTS][KH];
#pragma unroll
    for (int pt = 0; pt < PTS; pt++) {
        const float* qp = Qs + (grp * PTS + pt) * ROWQ + p * IK;
#pragma unroll
        for (int k = 0; k < KH; k++)
            q[pt][k] = *reinterpret_cast<const unsigned long long*>(qp + 2 * k);
    }

    float s[PTS] = {0.f, 0.f, 0.f, 0.f};

    for (int js = 0; js < DPAD; js += JSTAGE) {
        __syncthreads();               // Mb reuse guard
#pragma unroll
        for (int u = 0; u < (JSTAGE * DPAD) / THREADS; u++) {  // 2304/256 = 9
            int l = tid + u * THREADS;
            Mb[l] = g_MT[js * DPAD + l];
        }
        __syncthreads();

#pragma unroll
        for (int jj = 0; jj < JSTAGE; jj++) {
            const int j = js + jj;
            unsigned long long m[KH];
            const float* mp = Mb + jj * DPAD + p * IK;
#pragma unroll
            for (int k = 0; k < KH; k++)
                m[k] = *reinterpret_cast<const unsigned long long*>(mp + 2 * k);

#pragma unroll
            for (int pt = 0; pt < PTS; pt++) {
                unsigned long long t2 = 0ull;   // (+0.f, +0.f)
#pragma unroll
                for (int k = 0; k < KH; k++)
                    fma2(t2, q[pt][k], m[k]);
                float t  = pairsum(t2);
                float qj = Qs[(grp * PTS + pt) * ROWQ + j];
                s[pt] += t * qj;
            }
        }
    }

    // Reduce partial sums across the 8 i-slices (lanes p=0..7 of each group).
#pragma unroll
    for (int pt = 0; pt < PTS; pt++) {
#pragma unroll
        for (int off = 1; off < P; off <<= 1)
            s[pt] += __shfl_xor_sync(0xffffffffu, s[pt], off);
    }
    if (p == 0) {
        int nb = blockIdx.x * BM + grp * PTS;
#pragma unroll
        for (int pt = 0; pt < PTS; pt++)
            out[nb + pt] = s[pt];
    }
}

// ---------------------------------------------------------------------------
// Launch
// ---------------------------------------------------------------------------
extern "C" void kernel_launch(void* const* d_in, const int* in_sizes, int n_in,
                              void* d_out, int out_size) {
    const float* X = (const float*)d_in[0];   // x, 262144*10 floats (flat)
    const float* M = (const float*)d_in[1];   // M_inv, 286*286 floats
    float* out = (float*)d_out;               // 262144 floats

    k_transpose<<<(DPAD * DPAD + 255) / 256, 256>>>(M);
    k_veronese<<<(NPTS / 4) / 256, 256>>>(X);

    cudaFuncSetAttribute(k_quad, cudaFuncAttributeMaxDynamicSharedMemorySize,
                         SMEM_BYTES);
    k_quad<<<NPTS / BM, THREADS, SMEM_BYTES>>>(out);
}

// round 2
// speedup vs baseline: 1.2120x; 1.2120x over previous
#include <cuda_runtime.h>
#include <cstdint>

// Problem constants
#define NPTS 262144     // number of points
#define DIMS 10
#define DD   286        // comb(13,3)
#define DPAD 288        // padded (16 slices of 18)

typedef unsigned long long ull;

// 300 MB scratch: v_flat[r*NPTS + c] (flat-read as q-vectors by k_quad).
__device__ float g_scratch[(size_t)DD * NPTS];
// Symmetrized upper-triangular, column-major, padded:
//   g_ST[j*DPAD + i] = (i<j: M[i][j]+M[j][i]) (i==j: M[i][i]) (i>j or pad: 0)
__device__ float g_ST[DPAD * DPAD];

// ---------------------------------------------------------------------------
// Kernel 0: symmetrize + transpose + pad M_inv.
// ---------------------------------------------------------------------------
__global__ void k_prep(const float* __restrict__ M) {
    int idx = blockIdx.x * blockDim.x + threadIdx.x;
    if (idx >= DPAD * DPAD) return;
    int j = idx / DPAD;
    int i = idx - j * DPAD;
    float v = 0.0f;
    if (i < DD && j < DD) {
        if (i < j)       v = M[i * DD + j] + M[j * DD + i];
        else if (i == j) v = M[i * DD + i];
    }
    g_ST[idx] = v;
}

// ---------------------------------------------------------------------------
// Kernel 1: Veronese map (unchanged from passing version).
// Row order matches reference _exponent_nk: 1; x_j; (j<=a); (j<=a<=b).
// ---------------------------------------------------------------------------
__device__ __forceinline__ float4 f4mul(float4 a, float4 b) {
    return make_float4(a.x * b.x, a.y * b.y, a.z * b.z, a.w * b.w);
}

__global__ void k_veronese(const float* __restrict__ X) {
    int t = blockIdx.x * blockDim.x + threadIdx.x;
    int c = t * 4;

    float4 y[DIMS];
#pragma unroll
    for (int k = 0; k < DIMS; k++)
        y[k] = *reinterpret_cast<const float4*>(X + (size_t)k * NPTS + c);

    int r = 0;
    *reinterpret_cast<float4*>(g_scratch + (size_t)r * NPTS + c) =
        make_float4(1.f, 1.f, 1.f, 1.f);
    r++;
#pragma unroll
    for (int j = 0; j < DIMS; j++) {
        *reinterpret_cast<float4*>(g_scratch + (size_t)r * NPTS + c) = y[j];
        r++;
    }
#pragma unroll
    for (int j = 0; j < DIMS; j++)
#pragma unroll
        for (int a = j; a < DIMS; a++) {
            *reinterpret_cast<float4*>(g_scratch + (size_t)r * NPTS + c) =
                f4mul(y[j], y[a]);
            r++;
        }
#pragma unroll
    for (int j = 0; j < DIMS; j++)
#pragma unroll
        for (int a = j; a < DIMS; a++) {
            float4 t2 = f4mul(y[j], y[a]);
#pragma unroll
            for (int b = a; b < DIMS; b++) {
                *reinterpret_cast<float4*>(g_scratch + (size_t)r * NPTS + c) =
                    f4mul(t2, y[b]);
                r++;
            }
        }
}

// ---------------------------------------------------------------------------
// Kernel 2: triangular quadratic form, f32x2 FMA, M from L2 (LDG).
//   16 i-slices of 18; warp w owns slices {w, 15-w} (balanced: 306 cols each).
//   Lane l, sub-point pt -> point pt*32+l. q slices in registers, q_j from
//   smem (ROWQ=289, odd stride -> conflict-free), m via __ldg (L2-resident).
// ---------------------------------------------------------------------------
constexpr int BM      = 128;
constexpr int THREADS = 256;
constexpr int PTS     = 4;            // points per lane
constexpr int IK      = 18;           // slice width
constexpr int KH      = 9;            // f32x2 pairs per slice
constexpr int ROWQ    = 289;          // odd padded Qs row stride
constexpr int SMEM_FLOATS = BM * ROWQ + 8 * BM;   // Qs + reduction area
constexpr int SMEM_BYTES  = SMEM_FLOATS * 4;

__device__ __forceinline__ void fma2(ull& acc, ull a, ull b) {
    asm("fma.rn.f32x2 %0, %1, %2, %0;" : "+l"(acc) : "l"(a), "l"(b));
}
__device__ __forceinline__ float pairsum(ull v) {
    float lo = __uint_as_float((unsigned int)v);
    float hi = __uint_as_float((unsigned int)(v >> 32));
    return lo + hi;
}
__device__ __forceinline__ ull pack2(float lo, float hi) {
    ull r;
    asm("mov.b64 %0, {%1, %2};" : "=l"(r) : "f"(lo), "f"(hi));
    return r;
}

__global__ __launch_bounds__(THREADS, 1) void k_quad(float* __restrict__ out) {
    extern __shared__ float sm[];
    float* Qs = sm;                    // [BM][ROWQ]
    float* SR = sm + BM * ROWQ;        // [8][BM] partial sums

    const int tid  = threadIdx.x;
    const int w    = tid >> 5;         // warp 0..7
    const int lane = tid & 31;

    // Stage this block's 128 contiguous q-vectors into padded smem.
    const size_t base = (size_t)blockIdx.x * (BM * DD);
    for (int l = tid; l < BM * DD; l += THREADS) {
        int n = l / DD;
        int i = l - n * DD;
        Qs[n * ROWQ + i] = g_scratch[base + l];
    }
    if (tid < BM) {                    // zero i = 286,287 pad
        Qs[tid * ROWQ + 286] = 0.f;
        Qs[tid * ROWQ + 287] = 0.f;
    }
    __syncthreads();

    // Slice assignment: A = w, B = 15-w.
    const int i0a = 18 * w;            // also jstartA
    const int i0b = 270 - 18 * w;      // also jstartB  (i0a <= i0b)

    // Load this thread's q slices into register pairs.
    ull qa[PTS][KH], qb[PTS][KH];
    int rowb[PTS];
#pragma unroll
    for (int pt = 0; pt < PTS; pt++) {
        rowb[pt] = (pt * 32 + lane) * ROWQ;
        const float* qp = Qs + rowb[pt];
#pragma unroll
        for (int k = 0; k < KH; k++) {
            qa[pt][k] = pack2(qp[i0a + 2 * k], qp[i0a + 2 * k + 1]);
            qb[pt][k] = pack2(qp[i0b + 2 * k], qp[i0b + 2 * k + 1]);
        }
    }

    float s[PTS] = {0.f, 0.f, 0.f, 0.f};
    const ull* STa = reinterpret_cast<const ull*>(g_ST + i0a);
    const ull* STb = reinterpret_cast<const ull*>(g_ST + i0b);

    // Phase 1: columns [i0a, i0b) — slice A only.
#pragma unroll 2
    for (int j = i0a; j < i0b; j++) {
        ull ma[KH];
        const ull* mp = STa + (size_t)j * (DPAD / 2);
#pragma unroll
        for (int k = 0; k < KH; k++) ma[k] = __ldg(mp + k);
#pragma unroll
        for (int pt = 0; pt < PTS; pt++) {
            ull t2 = 0ull;
#pragma unroll
            for (int k = 0; k < KH; k++) fma2(t2, qa[pt][k], ma[k]);
            s[pt] = fmaf(pairsum(t2), Qs[rowb[pt] + j], s[pt]);
        }
    }

    // Phase 2: columns [i0b, 288) — slices A and B.
#pragma unroll 2
    for (int j = i0b; j < DPAD; j++) {
        ull ma[KH], mb[KH];
        const ull* mpa = STa + (size_t)j * (DPAD / 2);
        const ull* mpb = STb + (size_t)j * (DPAD / 2);
#pragma unroll
        for (int k = 0; k < KH; k++) { ma[k] = __ldg(mpa + k); mb[k] = __ldg(mpb + k); }
#pragma unroll
        for (int pt = 0; pt < PTS; pt++) {
            ull t2 = 0ull;
#pragma unroll
            for (int k = 0; k < KH; k++) fma2(t2, qa[pt][k], ma[k]);
            ull t3 = 0ull;
#pragma unroll
            for (int k = 0; k < KH; k++) fma2(t3, qb[pt][k], mb[k]);
            s[pt] = fmaf(pairsum(t2) + pairsum(t3), Qs[rowb[pt] + j], s[pt]);
        }
    }

    // Cross-warp reduction (8 partials per point).
#pragma unroll
    for (int pt = 0; pt < PTS; pt++)
        SR[w * BM + pt * 32 + lane] = s[pt];
    __syncthreads();

    if (tid < BM) {
        float acc = 0.f;
#pragma unroll
        for (int ww = 0; ww < 8; ww++) acc += SR[ww * BM + tid];
        out[blockIdx.x * BM + tid] = acc;
    }
}

// ---------------------------------------------------------------------------
// Launch
// ---------------------------------------------------------------------------
extern "C" void kernel_launch(void* const* d_in, const int* in_sizes, int n_in,
                              void* d_out, int out_size) {
    const float* X = (const float*)d_in[0];   // x (flat 10 x 262144)
    const float* M = (const float*)d_in[1];   // M_inv 286x286
    float* out = (float*)d_out;

    k_prep<<<(DPAD * DPAD + 255) / 256, 256>>>(M);
    k_veronese<<<(NPTS / 4) / 256, 256>>>(X);

    cudaFuncSetAttribute(k_quad, cudaFuncAttributeMaxDynamicSharedMemorySize,
                         SMEM_BYTES);
    k_quad<<<NPTS / BM, THREADS, SMEM_BYTES>>>(out);
}

// round 4
// speedup vs baseline: 1.3304x; 1.0977x over previous
#include <cuda_runtime.h>
#include <cstdint>

#define NPTS 262144
#define DIMS 10
#define DD   286       // comb(13,3)
#define DPAD 288       // 16 slices of 18

typedef unsigned long long ull;

// 300 MB scratch: v_flat[r*NPTS + c]. The reference's reshape makes q-vector n
// the CONTIGUOUS flat chunk v_flat[n*286 .. n*286+285] — this buffer IS the
// reshape semantics; do not fuse it away.
__device__ float g_scratch[(size_t)DD * NPTS];
// Symmetrized upper-tri, column-major, padded:
//   g_ST[j*DPAD+i] = (i<j: M[i][j]+M[j][i]) (i==j: M[i][i]) (else 0)
__device__ float g_ST[DPAD * DPAD];

// ---------------------------------------------------------------------------
// Kernel 0: symmetrize + transpose + pad M_inv.
// ---------------------------------------------------------------------------
__global__ void k_prep(const float* __restrict__ M) {
    int idx = blockIdx.x * blockDim.x + threadIdx.x;
    if (idx >= DPAD * DPAD) return;
    int j = idx / DPAD;
    int i = idx - j * DPAD;
    float v = 0.0f;
    if (i < DD && j < DD) {
        if (i < j)       v = M[i * DD + j] + M[j * DD + i];
        else if (i == j) v = M[i * DD + i];
    }
    g_ST[idx] = v;
}

// ---------------------------------------------------------------------------
// Kernel 1: Veronese map (row order matches reference _exponent_nk exactly).
// One thread per 4 consecutive columns.
// ---------------------------------------------------------------------------
__device__ __forceinline__ float4 f4mul(float4 a, float4 b) {
    return make_float4(a.x * b.x, a.y * b.y, a.z * b.z, a.w * b.w);
}

__global__ void k_veronese(const float* __restrict__ X) {
    int t = blockIdx.x * blockDim.x + threadIdx.x;
    int c = t * 4;

    float4 y[DIMS];
#pragma unroll
    for (int k = 0; k < DIMS; k++)
        y[k] = *reinterpret_cast<const float4*>(X + (size_t)k * NPTS + c);

    int r = 0;
    *reinterpret_cast<float4*>(g_scratch + (size_t)r * NPTS + c) =
        make_float4(1.f, 1.f, 1.f, 1.f);
    r++;
#pragma unroll
    for (int j = 0; j < DIMS; j++) {
        *reinterpret_cast<float4*>(g_scratch + (size_t)r * NPTS + c) = y[j];
        r++;
    }
#pragma unroll
    for (int j = 0; j < DIMS; j++)
#pragma unroll
        for (int a = j; a < DIMS; a++) {
            *reinterpret_cast<float4*>(g_scratch + (size_t)r * NPTS + c) =
                f4mul(y[j], y[a]);
            r++;
        }
#pragma unroll
    for (int j = 0; j < DIMS; j++)
#pragma unroll
        for (int a = j; a < DIMS; a++) {
            float4 t2 = f4mul(y[j], y[a]);
#pragma unroll
            for (int b = a; b < DIMS; b++) {
                *reinterpret_cast<float4*>(g_scratch + (size_t)r * NPTS + c) =
                    f4mul(t2, y[b]);
                r++;
            }
        }
}

// ---------------------------------------------------------------------------
// Kernel 2: triangular quadratic form.
//   512 threads = 16 warps; warp w owns i-slice slice(w) (18 rows) and the
//   column range [18*slice, 288). Lane covers 4 points. q slices in regs,
//   m rows from L2 via __ldg, s accumulated packed f32x2.
// ---------------------------------------------------------------------------
constexpr int BM      = 128;
constexpr int THREADS = 512;
constexpr int NW      = 16;
constexpr int PTS     = 4;
constexpr int KH      = 9;            // 18 floats = 9 f32x2 per slice
constexpr int ROWQ    = 289;          // odd stride -> conflict-free smem
constexpr int SMEM_BYTES = (BM * ROWQ + NW * BM) * 4;

__device__ __forceinline__ void fma2(ull& acc, ull a, ull b) {
    asm("fma.rn.f32x2 %0, %1, %2, %0;" : "+l"(acc) : "l"(a), "l"(b));
}
__device__ __forceinline__ float pairsum(ull v) {
    return __uint_as_float((unsigned int)v) +
           __uint_as_float((unsigned int)(v >> 32));
}
__device__ __forceinline__ ull pack2(float lo, float hi) {
    ull r;
    asm("mov.b64 %0, {%1, %2};" : "=l"(r) : "f"(lo), "f"(hi));
    return r;
}

__global__ __launch_bounds__(THREADS, 1) void k_quad(float* __restrict__ out) {
    extern __shared__ float sm[];
    float* Qs = sm;                    // [BM][ROWQ]
    float* SR = sm + BM * ROWQ;        // [NW][BM]

    const int tid  = threadIdx.x;
    const int w    = tid >> 5;
    const int lane = tid & 31;

    // ---- Stage 128 contiguous q-vectors from scratch (coalesced per warp):
    //      warp w copies rows n = w, w+16, ..., w+112.
    const size_t base = (size_t)blockIdx.x * (BM * DD);
#pragma unroll
    for (int rr = 0; rr < BM / NW; rr++) {
        const int n = w + rr * NW;
        const float* src = g_scratch + base + (size_t)n * DD;
        float* dst = Qs + n * ROWQ;
#pragma unroll
        for (int i = lane; i < DD; i += 32)
            dst[i] = src[i];
        if (lane < 2) dst[DD + lane] = 0.0f;   // pad i = 286, 287
    }
    __syncthreads();

    // ---- SMSP-balanced slice assignment (per-SMSP col total = 612) ----
    const int slice = (w < 8) ? w : 23 - w;
    const int i0 = 18 * slice;

    // q slices -> registers (stride 289 = 1 mod 32 -> conflict-free)
    ull q[PTS][KH];
    int rowq[PTS];
#pragma unroll
    for (int pt = 0; pt < PTS; pt++) {
        rowq[pt] = (pt * 32 + lane) * ROWQ;
        const float* qp = Qs + rowq[pt] + i0;
#pragma unroll
        for (int k = 0; k < KH; k++)
            q[pt][k] = pack2(qp[2 * k], qp[2 * k + 1]);
    }

    ull s2[PTS] = {0ull, 0ull, 0ull, 0ull};
    const ull* ST = reinterpret_cast<const ull*>(g_ST) + (i0 >> 1);

#pragma unroll 2
    for (int j = i0; j < DPAD; j++) {
        ull m[KH];
        const ull* mp = ST + (size_t)j * (DPAD / 2);
#pragma unroll
        for (int k = 0; k < KH; k++) m[k] = __ldg(mp + k);

#pragma unroll
        for (int pt = 0; pt < PTS; pt++) {
            ull t2 = 0ull;
#pragma unroll
            for (int k = 0; k < KH; k++) fma2(t2, q[pt][k], m[k]);
            float qj = Qs[rowq[pt] + j];
            fma2(s2[pt], t2, pack2(qj, qj));
        }
    }

    // ---- Cross-warp reduction: 16 partials per point ----
#pragma unroll
    for (int pt = 0; pt < PTS; pt++)
        SR[w * BM + pt * 32 + lane] = pairsum(s2[pt]);
    __syncthreads();

    if (tid < BM) {
        float acc = 0.0f;
#pragma unroll
        for (int ww = 0; ww < NW; ww++) acc += SR[ww * BM + tid];
        out[blockIdx.x * BM + tid] = acc;
    }
}

// ---------------------------------------------------------------------------
// Launch
// ---------------------------------------------------------------------------
extern "C" void kernel_launch(void* const* d_in, const int* in_sizes, int n_in,
                              void* d_out, int out_size) {
    const float* X = (const float*)d_in[0];   // x flat (xr[k][n] = X[k*NPTS+n])
    const float* M = (const float*)d_in[1];   // M_inv 286x286
    float* out = (float*)d_out;

    k_prep<<<(DPAD * DPAD + 255) / 256, 256>>>(M);
    k_veronese<<<(NPTS / 4) / 256, 256>>>(X);

    cudaFuncSetAttribute(k_quad, cudaFuncAttributeMaxDynamicSharedMemorySize,
                         SMEM_BYTES);
    k_quad<<<NPTS / BM, THREADS, SMEM_BYTES>>>(out);
}

// round 6
// speedup vs baseline: 1.4492x; 1.0893x over previous
#include <cuda_runtime.h>
#include <cuda_bf16.h>
#include <cstdint>

#define NPTS 262144
#define DIMS 10
#define DD   286            // comb(13,3)
#define KT   288            // K padded: 18 ksteps of 16
#define ROWE 296            // row stride in bf16 elems (592 B, ldmatrix-friendly)
#define ROWB 592            // row stride bytes
#define NB   32             // N columns per streamed B chunk
#define NCH  9              // 288 / 32 chunks
#define CHB  (NB * ROWB * 2)   // bytes per chunk (Bh + Bl) = 37888
#define BM   128

typedef unsigned long long ull;

// Flat Veronese scratch: v_flat[r*NPTS + c]; q-vector n = contiguous chunk
// [n*286,(n+1)*286) — this layout IS the reference reshape. Keep it.
__device__ float g_scratch[(size_t)DD * NPTS];
// B images, exact smem byte layout: [chunk 9][Bh 32x592B | Bl 32x592B].
__device__ uint4 g_B[NCH * CHB / 16];

// ---------------------------------------------------------------------------
// k_prepB: B[n][k] = M_inv[k][n] (286x286, zero-padded to 288x288),
// split bf16 hi + bf16 residual, written at final smem offsets.
// ---------------------------------------------------------------------------
__global__ void k_prepB(const float* __restrict__ M) {
    int t = blockIdx.x * blockDim.x + threadIdx.x;   // 288*288
    if (t >= KT * KT) return;
    int n = t / KT, k = t - n * KT;
    float v = (n < DD && k < DD) ? M[k * DD + n] : 0.0f;
    __nv_bfloat16 vh = __float2bfloat16(v);
    __nv_bfloat16 vl = __float2bfloat16(v - __bfloat162float(vh));
    __nv_bfloat16* B = reinterpret_cast<__nv_bfloat16*>(g_B);
    size_t cb = (size_t)(n >> 5) * (CHB / 2);        // chunk base (bf16 units)
    size_t off = cb + (size_t)(n & 31) * ROWE + k;
    B[off] = vh;
    B[off + NB * ROWE] = vl;                         // Bl half of the chunk
}

// ---------------------------------------------------------------------------
// k_veronese: unchanged (row order matches reference _exponent_nk exactly).
// ---------------------------------------------------------------------------
__device__ __forceinline__ float4 f4mul(float4 a, float4 b) {
    return make_float4(a.x * b.x, a.y * b.y, a.z * b.z, a.w * b.w);
}
__global__ void k_veronese(const float* __restrict__ X) {
    int t = blockIdx.x * blockDim.x + threadIdx.x;
    int c = t * 4;
    float4 y[DIMS];
#pragma unroll
    for (int k = 0; k < DIMS; k++)
        y[k] = *reinterpret_cast<const float4*>(X + (size_t)k * NPTS + c);
    int r = 0;
    *reinterpret_cast<float4*>(g_scratch + (size_t)r * NPTS + c) =
        make_float4(1.f, 1.f, 1.f, 1.f);
    r++;
#pragma unroll
    for (int j = 0; j < DIMS; j++) {
        *reinterpret_cast<float4*>(g_scratch + (size_t)r * NPTS + c) = y[j];
        r++;
    }
#pragma unroll
    for (int j = 0; j < DIMS; j++)
#pragma unroll
        for (int a = j; a < DIMS; a++) {
            *reinterpret_cast<float4*>(g_scratch + (size_t)r * NPTS + c) =
                f4mul(y[j], y[a]);
            r++;
        }
#pragma unroll
    for (int j = 0; j < DIMS; j++)
#pragma unroll
        for (int a = j; a < DIMS; a++) {
            float4 t2 = f4mul(y[j], y[a]);
#pragma unroll
            for (int b = a; b < DIMS; b++) {
                *reinterpret_cast<float4*>(g_scratch + (size_t)r * NPTS + c) =
                    f4mul(t2, y[b]);
                r++;
            }
        }
}

// ---------------------------------------------------------------------------
// Base-ISA PTX helpers (no sm_103a-gated instructions).
// ---------------------------------------------------------------------------
__device__ __forceinline__ void ldsm4(uint32_t r[4], uint32_t addr) {
    asm volatile(
        "ldmatrix.sync.aligned.m8n8.x4.shared.b16 {%0,%1,%2,%3}, [%4];"
        : "=r"(r[0]), "=r"(r[1]), "=r"(r[2]), "=r"(r[3]) : "r"(addr));
}
__device__ __forceinline__ void mma_bf16(float c[4], const uint32_t a[4],
                                         uint32_t b0, uint32_t b1) {
    asm volatile(
        "mma.sync.aligned.m16n8k16.row.col.f32.bf16.bf16.f32 "
        "{%0,%1,%2,%3}, {%4,%5,%6,%7}, {%8,%9}, {%0,%1,%2,%3};"
        : "+f"(c[0]), "+f"(c[1]), "+f"(c[2]), "+f"(c[3])
        : "r"(a[0]), "r"(a[1]), "r"(a[2]), "r"(a[3]), "r"(b0), "r"(b1));
}
__device__ __forceinline__ void bulk_g2s(uint32_t dst, const void* src,
                                         uint32_t bytes, uint32_t mbar) {
    asm volatile(
        "cp.async.bulk.shared::cta.global.mbarrier::complete_tx::bytes "
        "[%0], [%1], %2, [%3];"
        :: "r"(dst), "l"(src), "r"(bytes), "r"(mbar) : "memory");
}
__device__ __forceinline__ void mbar_init(uint32_t mbar, uint32_t cnt) {
    asm volatile("mbarrier.init.shared.b64 [%0], %1;" :: "r"(mbar), "r"(cnt)
                 : "memory");
}
__device__ __forceinline__ void mbar_expect(uint32_t mbar, uint32_t bytes) {
    asm volatile("mbarrier.arrive.expect_tx.shared.b64 _, [%0], %1;"
                 :: "r"(mbar), "r"(bytes) : "memory");
}
__device__ __forceinline__ void mbar_arrive(uint32_t mbar) {
    asm volatile("mbarrier.arrive.shared.b64 _, [%0];" :: "r"(mbar)
                 : "memory");
}
__device__ __forceinline__ void mbar_wait(uint32_t mbar, uint32_t parity) {
    asm volatile(
        "{\n\t.reg .pred P1;\n\t"
        "W_%=:\n\t"
        "mbarrier.try_wait.parity.acquire.cta.shared::cta.b64 P1, [%0], %1, 0x989680;\n\t"
        "@P1 bra.uni D_%=;\n\t"
        "bra.uni W_%=;\n\t"
        "D_%=:\n\t}"
        :: "r"(mbar), "r"(parity) : "memory");
}
__device__ __forceinline__ uint32_t cvt2bf(float hi, float lo) {
    uint32_t r;
    asm("cvt.rn.bf16x2.f32 %0, %1, %2;" : "=r"(r) : "f"(hi), "f"(lo));
    return r;
}

// SMEM map (bytes from dynamic smem base)
constexpr int SM_FULL0 = 0,  SM_FULL1 = 8, SM_EMPTY0 = 16, SM_EMPTY1 = 24;
constexpr int SM_AH = 1024;
constexpr int SM_AL = SM_AH + BM * ROWB;       // 76800
constexpr int SM_B  = SM_AL + BM * ROWB;       // 152576
constexpr int SMEM_TOTAL = SM_B + 2 * CHB;     // 228352

// ---------------------------------------------------------------------------
// k_main: A-split fill -> double-buffered B stream + 3-product HMMA GEMM
// with fused T·q epilogue.
// ---------------------------------------------------------------------------
__global__ __launch_bounds__(256, 1) void k_main(float* __restrict__ out) {
    extern __shared__ char sm[];
    const uint32_t smb = (uint32_t)__cvta_generic_to_shared(sm);
    const int tid = threadIdx.x, w = tid >> 5, lane = tid & 31;

    if (tid == 0) {
        mbar_init(smb + SM_FULL0, 1);
        mbar_init(smb + SM_FULL1, 1);
        mbar_init(smb + SM_EMPTY0, 256);
        mbar_init(smb + SM_EMPTY1, 256);
    }
    __syncthreads();

    // ---- A fill: warp w builds rows 16w..16w+15 (hi/lo bf16 split) ----
    {
        const float* src = g_scratch + (size_t)blockIdx.x * (BM * DD);
#pragma unroll
        for (int rr = 0; rr < 16; rr++) {
            const int r = w * 16 + rr;
            const float* qr = src + (size_t)r * DD;
            char* ah = sm + SM_AH + r * ROWB;
            char* al = sm + SM_AL + r * ROWB;
            for (int ip = lane; ip < 144; ip += 32) {   // 144 f32 pairs = 288
                float q0 = 0.f, q1 = 0.f;
                if (ip < 143) {
                    float2 v = *reinterpret_cast<const float2*>(qr + 2 * ip);
                    q0 = v.x; q1 = v.y;
                }
                uint32_t h2 = cvt2bf(q1, q0);
                float h0 = __uint_as_float(h2 << 16);
                float h1 = __uint_as_float(h2 & 0xffff0000u);
                uint32_t l2 = cvt2bf(q1 - h1, q0 - h0);
                *reinterpret_cast<uint32_t*>(ah + ip * 4) = h2;
                *reinterpret_cast<uint32_t*>(al + ip * 4) = l2;
            }
        }
    }
    // Kick chunk 0 copy.
    if (tid == 0) {
        mbar_expect(smb + SM_FULL0, CHB);
        bulk_g2s(smb + SM_B, g_B, CHB, smb + SM_FULL0);
    }
    __syncthreads();   // A complete for all warps

    // ldmatrix lane address components
    const uint32_t aRow = smb + SM_AH + (w * 16 + (lane & 15)) * ROWB +
                          (lane >> 4) * 16;
    const uint32_t bOff = (((lane >> 4) & 1) * 8 + (lane & 7)) * ROWB +
                          ((lane >> 3) & 1) * 16;

    float out0 = 0.f, out1 = 0.f;
    const int r0 = w * 16 + (lane >> 2);     // C-fragment rows r0, r0+8
    const uint32_t qh0 = smb + SM_AH + r0 * ROWB + (lane & 3) * 4;
    const uint32_t ql0 = smb + SM_AL + r0 * ROWB + (lane & 3) * 4;

    for (int c = 0; c < NCH; c++) {
        const int b = c & 1;
        // Producer: prefetch chunk c+1 into the other buffer.
        if (tid == 0 && c + 1 < NCH) {
            const int b2 = (c + 1) & 1;
            if (c >= 1)
                mbar_wait(smb + SM_EMPTY0 + 8 * b2, ((c - 1) >> 1) & 1);
            mbar_expect(smb + SM_FULL0 + 8 * b2, CHB);
            bulk_g2s(smb + SM_B + b2 * CHB,
                     reinterpret_cast<const char*>(g_B) + (size_t)(c + 1) * CHB,
                     CHB, smb + SM_FULL0 + 8 * b2);
        }
        mbar_wait(smb + SM_FULL0 + 8 * b, (c >> 1) & 1);

        const uint32_t bh = smb + SM_B + b * CHB + bOff;
        const uint32_t bl = bh + NB * ROWB;

        float C0[4] = {0,0,0,0}, C1[4] = {0,0,0,0};
        float C2[4] = {0,0,0,0}, C3[4] = {0,0,0,0};
#pragma unroll 3
        for (int k = 0; k < 18; k++) {
            uint32_t ah[4], al[4], h0[4], h1[4], l0[4], l1[4];
            ldsm4(ah, aRow + k * 32);
            ldsm4(al, aRow + (SM_AL - SM_AH) + k * 32);
            ldsm4(h0, bh + k * 32);                 // Bh rows 0-15
            ldsm4(h1, bh + 16 * ROWB + k * 32);     // Bh rows 16-31
            ldsm4(l0, bl + k * 32);                 // Bl rows 0-15
            ldsm4(l1, bl + 16 * ROWB + k * 32);     // Bl rows 16-31
            mma_bf16(C0, ah, h0[0], h0[1]);
            mma_bf16(C1, ah, h0[2], h0[3]);
            mma_bf16(C2, ah, h1[0], h1[1]);
            mma_bf16(C3, ah, h1[2], h1[3]);
            mma_bf16(C0, ah, l0[0], l0[1]);
            mma_bf16(C1, ah, l0[2], l0[3]);
            mma_bf16(C2, ah, l1[0], l1[1]);
            mma_bf16(C3, ah, l1[2], l1[3]);
            mma_bf16(C0, al, h0[0], h0[1]);
            mma_bf16(C1, al, h0[2], h0[3]);
            mma_bf16(C2, al, h1[0], h1[1]);
            mma_bf16(C3, al, h1[2], h1[3]);
        }
        mbar_arrive(smb + SM_EMPTY0 + 8 * b);   // buffer b free

        // ---- Fused epilogue: out += C ∘ q over this chunk's 32 columns ----
        const int jb = c * 32;
        const float* Cn[4] = {C0, C1, C2, C3};
#pragma unroll
        for (int nc = 0; nc < 4; nc++) {
            const uint32_t jo = (jb + nc * 8) * 2;  // byte offset of j0 pair
            uint32_t vh, vl, wh, wl;
            asm volatile("ld.shared.b32 %0, [%1];" : "=r"(vh) : "r"(qh0 + jo));
            asm volatile("ld.shared.b32 %0, [%1];" : "=r"(vl) : "r"(ql0 + jo));
            asm volatile("ld.shared.b32 %0, [%1];" : "=r"(wh)
                         : "r"(qh0 + 8 * ROWB + jo));
            asm volatile("ld.shared.b32 %0, [%1];" : "=r"(wl)
                         : "r"(ql0 + 8 * ROWB + jo));
            float qe = __uint_as_float(vh << 16) + __uint_as_float(vl << 16);
            float qo = __uint_as_float(vh & 0xffff0000u) +
                       __uint_as_float(vl & 0xffff0000u);
            float re = __uint_as_float(wh << 16) + __uint_as_float(wl << 16);
            float ro = __uint_as_float(wh & 0xffff0000u) +
                       __uint_as_float(wl & 0xffff0000u);
            out0 = fmaf(Cn[nc][0], qe, out0);
            out0 = fmaf(Cn[nc][1], qo, out0);
            out1 = fmaf(Cn[nc][2], re, out1);
            out1 = fmaf(Cn[nc][3], ro, out1);
        }
    }

    // Reduce the 4 j-phases held by each lane quad.
    out0 += __shfl_xor_sync(0xffffffffu, out0, 1);
    out0 += __shfl_xor_sync(0xffffffffu, out0, 2);
    out1 += __shfl_xor_sync(0xffffffffu, out1, 1);
    out1 += __shfl_xor_sync(0xffffffffu, out1, 2);
    if ((lane & 3) == 0) {
        out[blockIdx.x * BM + r0]     = out0;
        out[blockIdx.x * BM + r0 + 8] = out1;
    }
}

// ---------------------------------------------------------------------------
// Launch
// ---------------------------------------------------------------------------
extern "C" void kernel_launch(void* const* d_in, const int* in_sizes, int n_in,
                              void* d_out, int out_size) {
    const float* X = (const float*)d_in[0];   // x flat (xr[k][n] = X[k*NPTS+n])
    const float* M = (const float*)d_in[1];   // M_inv 286x286
    float* out = (float*)d_out;

    k_prepB<<<(KT * KT + 255) / 256, 256>>>(M);
    k_veronese<<<(NPTS / 4) / 256, 256>>>(X);

    cudaFuncSetAttribute(k_main, cudaFuncAttributeMaxDynamicSharedMemorySize,
                         SMEM_TOTAL);
    k_main<<<NPTS / BM, 256, SMEM_TOTAL>>>(out);
}